// round 1
// baseline (speedup 1.0000x reference)
#include <cuda_runtime.h>
#include <cstdint>
#include <cstddef>

#define LAT 128
#define NNODES 50000
#define NEDGES 400000
#define EPSV 1e-5f

// Scratch: h0, h1, agg (node-sized) + e0, e1 (edge-sized), all [*,128] fp32.
__device__ float g_scratch[(size_t)(3 * NNODES + 2 * NEDGES) * LAT];

// ---------------------------------------------------------------------------
// Fused: gather/concat -> Linear(K,128)+ReLU -> Linear(128,128)+ReLU -> LN
//        -> (optional residual add) -> (store | atomic scatter-add)
// GMODE 0: raw dense input [nRows, KREAL] (encoders; K padded to 16)
// GMODE 1: 3-block gather  [ hA[idxA[r]] | hB[idxB[r]] | eIn[r] ]  (K=384)
// GMODE 2: 2-block direct  [ hA[r] | hB[r] ]                      (K=256)
// ATOMIC:  atomicAdd rows into outp[scatIdx[r]] instead of storing at r.
// ---------------------------------------------------------------------------
template <int K, int KREAL, int GMODE, bool ATOMIC>
__global__ __launch_bounds__(256) void fused_mlp(
    const float* __restrict__ raw,
    const float* __restrict__ hA, const float* __restrict__ hB,
    const float* __restrict__ eIn,
    const int* __restrict__ idxA, const int* __restrict__ idxB,
    const float* __restrict__ W1, const float* __restrict__ B1,
    const float* __restrict__ W2, const float* __restrict__ B2,
    const float* __restrict__ G, const float* __restrict__ BE,
    const float* __restrict__ res,
    float* __restrict__ outp,
    const int* __restrict__ scatIdx,
    int nRows)
{
    extern __shared__ float smem[];
    float* As = smem;               // [16][129]
    float* Bs = As + 16 * 129;      // [16][128]
    float* H1 = Bs + 16 * 128;      // [128][129]  (hidden, then reused for LN)

    const int tid = threadIdx.x;
    const int tx = tid & 15, ty = tid >> 4;
    const int blockRow = blockIdx.x * 128;

    float c[8][8];
#pragma unroll
    for (int i = 0; i < 8; i++)
#pragma unroll
        for (int j = 0; j < 8; j++) c[i][j] = 0.f;

    // Per-thread fixed gather coordinates for A-tile loads.
    const int r0 = tid >> 2;            // 0..63
    const int r1 = r0 + 64;             // 64..127
    const int kq = (tid & 3) * 4;       // 0,4,8,12 within 16-wide k tile
    const int g0 = blockRow + r0;
    const int g1 = blockRow + r1;
    int iA0 = 0, iA1 = 0, iB0 = 0, iB1 = 0;
    if constexpr (GMODE == 1) {
        iA0 = (g0 < nRows) ? idxA[g0] : 0;
        iA1 = (g1 < nRows) ? idxA[g1] : 0;
        iB0 = (g0 < nRows) ? idxB[g0] : 0;
        iB1 = (g1 < nRows) ? idxB[g1] : 0;
    }

    // ---------------- layer 1: [128 rows, K] @ [K, 128] ----------------
    constexpr int NT = K / 16;
    for (int kt = 0; kt < NT; kt++) {
        if constexpr (GMODE == 0) {
#pragma unroll
            for (int it = 0; it < 8; it++) {
                int idx = tid + 256 * it;
                int row = idx >> 4, k = idx & 15;
                int gr = blockRow + row;
                float v = (k < KREAL && gr < nRows) ? raw[(size_t)gr * KREAL + k] : 0.f;
                As[k * 129 + row] = v;
            }
        } else {
            const int blk = kt >> 3;
            const int kk0 = (kt & 7) * 16;
            const float* base;
            int ri0, ri1;
            if constexpr (GMODE == 2) {
                base = (blk == 0) ? hA : hB;
                ri0 = g0; ri1 = g1;
            } else {
                if (blk == 0)      { base = hA;  ri0 = iA0; ri1 = iA1; }
                else if (blk == 1) { base = hB;  ri0 = iB0; ri1 = iB1; }
                else               { base = eIn; ri0 = g0;  ri1 = g1;  }
            }
            float4 v0 = make_float4(0.f, 0.f, 0.f, 0.f), v1 = v0;
            if (g0 < nRows) v0 = *(const float4*)&base[(size_t)ri0 * LAT + kk0 + kq];
            if (g1 < nRows) v1 = *(const float4*)&base[(size_t)ri1 * LAT + kk0 + kq];
            As[(kq + 0) * 129 + r0] = v0.x;
            As[(kq + 1) * 129 + r0] = v0.y;
            As[(kq + 2) * 129 + r0] = v0.z;
            As[(kq + 3) * 129 + r0] = v0.w;
            As[(kq + 0) * 129 + r1] = v1.x;
            As[(kq + 1) * 129 + r1] = v1.y;
            As[(kq + 2) * 129 + r1] = v1.z;
            As[(kq + 3) * 129 + r1] = v1.w;
        }
        // W1 tile [16, 128]
#pragma unroll
        for (int it = 0; it < 2; it++) {
            int f = tid + 256 * it;           // float4 index among 512
            int krow = f >> 5, col4 = (f & 31) * 4;
            int kk = kt * 16 + krow;
            float4 bv = make_float4(0.f, 0.f, 0.f, 0.f);
            if (KREAL == K || kk < KREAL)
                bv = *(const float4*)&W1[(size_t)kk * LAT + col4];
            *(float4*)&Bs[krow * LAT + col4] = bv;
        }
        __syncthreads();
#pragma unroll
        for (int k = 0; k < 16; k++) {
            float a[8];
#pragma unroll
            for (int i = 0; i < 8; i++) a[i] = As[k * 129 + ty * 8 + i];
            float4 bb0 = *(float4*)&Bs[k * LAT + tx * 8];
            float4 bb1 = *(float4*)&Bs[k * LAT + tx * 8 + 4];
            float b[8] = {bb0.x, bb0.y, bb0.z, bb0.w, bb1.x, bb1.y, bb1.z, bb1.w};
#pragma unroll
            for (int i = 0; i < 8; i++)
#pragma unroll
                for (int j = 0; j < 8; j++) c[i][j] = fmaf(a[i], b[j], c[i][j]);
        }
        __syncthreads();
    }

    // bias1 + ReLU -> H1[hid][row] (transposed so layer2 reads it like As)
    {
        float4 q0 = *(const float4*)&B1[tx * 8];
        float4 q1 = *(const float4*)&B1[tx * 8 + 4];
        float bb[8] = {q0.x, q0.y, q0.z, q0.w, q1.x, q1.y, q1.z, q1.w};
#pragma unroll
        for (int i = 0; i < 8; i++)
#pragma unroll
            for (int j = 0; j < 8; j++)
                H1[(tx * 8 + j) * 129 + ty * 8 + i] = fmaxf(c[i][j] + bb[j], 0.f);
    }
    __syncthreads();

    // ---------------- layer 2: [128,128] @ [128,128] ----------------
#pragma unroll
    for (int i = 0; i < 8; i++)
#pragma unroll
        for (int j = 0; j < 8; j++) c[i][j] = 0.f;

    for (int kt = 0; kt < 8; kt++) {
#pragma unroll
        for (int it = 0; it < 2; it++) {
            int f = tid + 256 * it;
            int krow = f >> 5, col4 = (f & 31) * 4;
            *(float4*)&Bs[krow * LAT + col4] =
                *(const float4*)&W2[(size_t)(kt * 16 + krow) * LAT + col4];
        }
        __syncthreads();
#pragma unroll
        for (int k = 0; k < 16; k++) {
            float a[8];
#pragma unroll
            for (int i = 0; i < 8; i++) a[i] = H1[(kt * 16 + k) * 129 + ty * 8 + i];
            float4 bb0 = *(float4*)&Bs[k * LAT + tx * 8];
            float4 bb1 = *(float4*)&Bs[k * LAT + tx * 8 + 4];
            float b[8] = {bb0.x, bb0.y, bb0.z, bb0.w, bb1.x, bb1.y, bb1.z, bb1.w};
#pragma unroll
            for (int i = 0; i < 8; i++)
#pragma unroll
                for (int j = 0; j < 8; j++) c[i][j] = fmaf(a[i], b[j], c[i][j]);
        }
        __syncthreads();
    }

    // bias2 + ReLU -> H1 reused as S[row][col]
    {
        float4 q0 = *(const float4*)&B2[tx * 8];
        float4 q1 = *(const float4*)&B2[tx * 8 + 4];
        float bb[8] = {q0.x, q0.y, q0.z, q0.w, q1.x, q1.y, q1.z, q1.w};
#pragma unroll
        for (int i = 0; i < 8; i++)
#pragma unroll
            for (int j = 0; j < 8; j++)
                H1[(ty * 8 + i) * 129 + tx * 8 + j] = fmaxf(c[i][j] + bb[j], 0.f);
    }
    __syncthreads();

    // ---------------- LayerNorm + residual + output ----------------
    const int warp = tid >> 5, lane = tid & 31;
    float gq[4], beq[4];
#pragma unroll
    for (int q = 0; q < 4; q++) {
        gq[q] = G[lane + 32 * q];
        beq[q] = BE[lane + 32 * q];
    }
    for (int rr = 0; rr < 16; rr++) {
        int row = warp * 16 + rr;
        int grow = blockRow + row;
        float v[4];
#pragma unroll
        for (int q = 0; q < 4; q++) v[q] = H1[row * 129 + lane + 32 * q];
        float s = v[0] + v[1] + v[2] + v[3];
#pragma unroll
        for (int o = 16; o > 0; o >>= 1) s += __shfl_xor_sync(0xffffffffu, s, o);
        float mu = s * (1.0f / 128.0f);
        float sq = 0.f;
#pragma unroll
        for (int q = 0; q < 4; q++) {
            float d = v[q] - mu;
            sq = fmaf(d, d, sq);
        }
#pragma unroll
        for (int o = 16; o > 0; o >>= 1) sq += __shfl_xor_sync(0xffffffffu, sq, o);
        float rs = rsqrtf(sq * (1.0f / 128.0f) + EPSV);

        if (grow < nRows) {
            if constexpr (ATOMIC) {
                int drow = scatIdx[grow];
#pragma unroll
                for (int q = 0; q < 4; q++) {
                    int cc = lane + 32 * q;
                    float ov = (v[q] - mu) * rs * gq[q] + beq[q];
                    atomicAdd(&outp[(size_t)drow * LAT + cc], ov);
                }
            } else {
#pragma unroll
                for (int q = 0; q < 4; q++) {
                    int cc = lane + 32 * q;
                    float ov = (v[q] - mu) * rs * gq[q] + beq[q];
                    if (res) ov += res[(size_t)grow * LAT + cc];
                    outp[(size_t)grow * LAT + cc] = ov;
                }
            }
        }
    }
}

// ---------------------------------------------------------------------------
// Decoder: relu(h @ W1 + b1) @ W2 + b2, out width 3. One warp per row.
// ---------------------------------------------------------------------------
__global__ __launch_bounds__(256) void decoder_kernel(
    const float* __restrict__ h,
    const float* __restrict__ W1, const float* __restrict__ B1,
    const float* __restrict__ W2, const float* __restrict__ B2,
    float* __restrict__ out, int n)
{
    extern __shared__ float s[];
    float* W1s = s;              // [128][128]
    float* hs = s + 128 * 128;   // [8][128]
    int tid = threadIdx.x;
#pragma unroll
    for (int it = 0; it < 16; it++) {
        int f = tid + 256 * it;  // float4 index among 4096
        *(float4*)&W1s[f * 4] = *(const float4*)&W1[f * 4];
    }
    int warp = tid >> 5, lane = tid & 31;
    int row = blockIdx.x * 8 + warp;
#pragma unroll
    for (int q = 0; q < 4; q++)
        hs[warp * 128 + lane + 32 * q] =
            (row < n) ? h[(size_t)row * LAT + lane + 32 * q] : 0.f;
    __syncthreads();

    float acc[4];
#pragma unroll
    for (int q = 0; q < 4; q++) acc[q] = B1[lane + 32 * q];
    for (int k = 0; k < 128; k++) {
        float hv = hs[warp * 128 + k];
#pragma unroll
        for (int q = 0; q < 4; q++)
            acc[q] = fmaf(hv, W1s[k * 128 + lane + 32 * q], acc[q]);
    }
#pragma unroll
    for (int q = 0; q < 4; q++) acc[q] = fmaxf(acc[q], 0.f);

    float o[3];
#pragma unroll
    for (int oo = 0; oo < 3; oo++) {
        float p = 0.f;
#pragma unroll
        for (int q = 0; q < 4; q++)
            p = fmaf(acc[q], W2[(size_t)(lane + 32 * q) * 3 + oo], p);
#pragma unroll
        for (int off = 16; off > 0; off >>= 1)
            p += __shfl_xor_sync(0xffffffffu, p, off);
        o[oo] = p;
    }
    if (lane == 0 && row < n) {
        out[(size_t)row * 3 + 0] = o[0] + B2[0];
        out[(size_t)row * 3 + 1] = o[1] + B2[1];
        out[(size_t)row * 3 + 2] = o[2] + B2[2];
    }
}

__global__ void zero_kernel(float* __restrict__ p, int n)
{
    int i = blockIdx.x * blockDim.x + threadIdx.x;
    if (i < n) p[i] = 0.f;
}

// ---------------------------------------------------------------------------
extern "C" void kernel_launch(void* const* d_in, const int* in_sizes, int n_in,
                              void* d_out, int out_size)
{
    (void)in_sizes; (void)n_in; (void)out_size;
    const float* x  = (const float*)d_in[0];
    const float* ea = (const float*)d_in[1];
    const int*   ei = (const int*)d_in[2];
    const int* src = ei;             // edge_index[0]
    const int* dst = ei + NEDGES;    // edge_index[1]

    const float* ne_w1 = (const float*)d_in[3];
    const float* ne_b1 = (const float*)d_in[4];
    const float* ne_w2 = (const float*)d_in[5];
    const float* ne_b2 = (const float*)d_in[6];
    const float* ne_g  = (const float*)d_in[7];
    const float* ne_be = (const float*)d_in[8];
    const float* ee_w1 = (const float*)d_in[9];
    const float* ee_b1 = (const float*)d_in[10];
    const float* ee_w2 = (const float*)d_in[11];
    const float* ee_b2 = (const float*)d_in[12];
    const float* ee_g  = (const float*)d_in[13];
    const float* ee_be = (const float*)d_in[14];
    const float* em_w1 = (const float*)d_in[15];
    const float* em_b1 = (const float*)d_in[16];
    const float* em_w2 = (const float*)d_in[17];
    const float* em_b2 = (const float*)d_in[18];
    const float* em_g  = (const float*)d_in[19];
    const float* em_be = (const float*)d_in[20];
    const float* nm_w1 = (const float*)d_in[21];
    const float* nm_b1 = (const float*)d_in[22];
    const float* nm_w2 = (const float*)d_in[23];
    const float* nm_b2 = (const float*)d_in[24];
    const float* nm_g  = (const float*)d_in[25];
    const float* nm_be = (const float*)d_in[26];
    const float* dw1   = (const float*)d_in[27];
    const float* db1   = (const float*)d_in[28];
    const float* dw2   = (const float*)d_in[29];
    const float* db2   = (const float*)d_in[30];

    float* base = nullptr;
    cudaGetSymbolAddress((void**)&base, g_scratch);
    float* h0  = base;
    float* h1  = h0 + (size_t)NNODES * LAT;
    float* agg = h1 + (size_t)NNODES * LAT;
    float* e0  = agg + (size_t)NNODES * LAT;
    float* e1  = e0 + (size_t)NEDGES * LAT;

    const int SM = (16 * 129 + 16 * 128 + 128 * 129) * (int)sizeof(float);  // 82496
    const int DSM = (128 * 128 + 8 * 128) * (int)sizeof(float);             // 69632
    cudaFuncSetAttribute(fused_mlp<16, 3, 0, false>,
                         cudaFuncAttributeMaxDynamicSharedMemorySize, SM);
    cudaFuncSetAttribute(fused_mlp<16, 4, 0, false>,
                         cudaFuncAttributeMaxDynamicSharedMemorySize, SM);
    cudaFuncSetAttribute(fused_mlp<384, 384, 1, true>,
                         cudaFuncAttributeMaxDynamicSharedMemorySize, SM);
    cudaFuncSetAttribute(fused_mlp<384, 384, 1, false>,
                         cudaFuncAttributeMaxDynamicSharedMemorySize, SM);
    cudaFuncSetAttribute(fused_mlp<256, 256, 2, false>,
                         cudaFuncAttributeMaxDynamicSharedMemorySize, SM);
    cudaFuncSetAttribute(decoder_kernel,
                         cudaFuncAttributeMaxDynamicSharedMemorySize, DSM);

    dim3 blk(256);
    const int ntiles = (NNODES + 127) / 128;  // 391
    const int etiles = NEDGES / 128;          // 3125

    // Encoders
    fused_mlp<16, 3, 0, false><<<ntiles, blk, SM>>>(
        x, nullptr, nullptr, nullptr, nullptr, nullptr,
        ne_w1, ne_b1, ne_w2, ne_b2, ne_g, ne_be,
        nullptr, h0, nullptr, NNODES);
    fused_mlp<16, 4, 0, false><<<etiles, blk, SM>>>(
        ea, nullptr, nullptr, nullptr, nullptr, nullptr,
        ee_w1, ee_b1, ee_w2, ee_b2, ee_g, ee_be,
        nullptr, e0, nullptr, NEDGES);

    float *hc = h0, *hn = h1, *ec = e0, *en = e1;
    for (int s = 0; s < 5; s++) {
        zero_kernel<<<(NNODES * LAT + 1023) / 1024, 1024>>>(agg, NNODES * LAT);
        // messages: ln_mlp(cat(h[dst], h[src], e)) scattered-add into agg[dst]
        fused_mlp<384, 384, 1, true><<<etiles, blk, SM>>>(
            nullptr, hc, hc, ec, dst, src,
            em_w1, em_b1, em_w2, em_b2, em_g, em_be,
            nullptr, agg, dst, NEDGES);
        // edge update: ln_mlp(cat(h[src], h[dst], e)) + e
        fused_mlp<384, 384, 1, false><<<etiles, blk, SM>>>(
            nullptr, hc, hc, ec, src, dst,
            em_w1, em_b1, em_w2, em_b2, em_g, em_be,
            ec, en, nullptr, NEDGES);
        // node update: ln_mlp(cat(agg, h)) + h
        fused_mlp<256, 256, 2, false><<<ntiles, blk, SM>>>(
            nullptr, agg, hc, nullptr, nullptr, nullptr,
            nm_w1, nm_b1, nm_w2, nm_b2, nm_g, nm_be,
            hc, hn, nullptr, NNODES);
        float* t;
        t = hc; hc = hn; hn = t;
        t = ec; ec = en; en = t;
    }

    decoder_kernel<<<(NNODES + 7) / 8, blk, DSM>>>(
        hc, dw1, db1, dw2, db2, (float*)d_out, NNODES);
}